// round 6
// baseline (speedup 1.0000x reference)
#include <cuda_runtime.h>
#include <cstdint>

#define NN 100000
#define NE 800000
#define HD 64

// ---------------- device scratch ---------------------------------------------
__device__ __align__(16) float g_bufA[(size_t)NN * HD];
__device__ __align__(16) float g_bufB[(size_t)NN * HD];
__device__ int   g_deg [NN];
__device__ float g_dinv[NN];
__device__ int   g_off [NN];
__device__ int   g_pos [NN];
__device__ int   g_csr [NE + NN];
__device__ int   g_bsum[128];
__device__ int   g_is64;

// ---------------- edge dtype detection (int32 vs int64) ----------------------
__global__ void k_detect(const long long* __restrict__ ei64, int n) {
    if (threadIdx.x == 0 && blockIdx.x == 0) {
        int is64 = 1;
        #pragma unroll
        for (int k = 0; k < 16; k++) {
            long long v = ei64[k];
            if (v < 0 || v >= (long long)n) { is64 = 0; break; }
        }
        g_is64 = is64;
    }
}

__device__ __forceinline__ int edge_at(const int* __restrict__ p32,
                                       const long long* __restrict__ p64,
                                       int idx) {
    return g_is64 ? (int)__ldg(&p64[idx]) : __ldg(&p32[idx]);
}

// ---------------- CSR construction -------------------------------------------
__global__ void k_count(const int* __restrict__ e32,
                        const long long* __restrict__ e64, int E) {
    int e = blockIdx.x * blockDim.x + threadIdx.x;
    if (e < E) atomicAdd(&g_deg[edge_at(e32, e64, E + e)], 1);
}

// shuffle-based block scan, 1024 threads/block. deg := edge_count + 1 (self-loop).
__global__ void __launch_bounds__(1024) k_scanA(int n) {
    __shared__ int wsum[32];
    int i    = blockIdx.x * 1024 + threadIdx.x;
    int lane = threadIdx.x & 31, wid = threadIdx.x >> 5;
    int v = 0;
    if (i < n) {
        v = g_deg[i] + 1;
        g_deg[i]  = v;
        g_dinv[i] = rsqrtf((float)v);
    }
    int s = v;
    #pragma unroll
    for (int d = 1; d < 32; d <<= 1) {
        int t = __shfl_up_sync(0xffffffffu, s, d);
        if (lane >= d) s += t;
    }
    if (lane == 31) wsum[wid] = s;
    __syncthreads();
    if (wid == 0) {
        int ws = wsum[lane];
        #pragma unroll
        for (int d = 1; d < 32; d <<= 1) {
            int t = __shfl_up_sync(0xffffffffu, ws, d);
            if (lane >= d) ws += t;
        }
        wsum[lane] = ws;
    }
    __syncthreads();
    if (i < n) g_off[i] = (wid ? wsum[wid - 1] : 0) + s - v;   // exclusive
    if (threadIdx.x == 0) g_bsum[blockIdx.x] = wsum[31];        // block total
}

// parallel exclusive scan of <=128 block sums, one block
__global__ void k_scanB(int nb) {
    __shared__ int wsum[4];
    int t = threadIdx.x, lane = t & 31, wid = t >> 5;
    int v = (t < nb) ? g_bsum[t] : 0;
    int s = v;
    #pragma unroll
    for (int d = 1; d < 32; d <<= 1) {
        int u = __shfl_up_sync(0xffffffffu, s, d);
        if (lane >= d) s += u;
    }
    if (lane == 31) wsum[wid] = s;
    __syncthreads();
    if (t == 0) { int r = 0; for (int w = 0; w < 4; w++) { int x = wsum[w]; wsum[w] = r; r += x; } }
    __syncthreads();
    if (t < nb) g_bsum[t] = wsum[wid] + s - v;
}

__global__ void k_scanC(int n) {
    int i = blockIdx.x * blockDim.x + threadIdx.x;
    if (i < n) {
        int o = g_off[i] + g_bsum[i >> 10];
        g_off[i] = o;
        g_pos[i] = o;
    }
}

__global__ void k_fill(const int* __restrict__ e32,
                       const long long* __restrict__ e64, int E, int n) {
    int e = blockIdx.x * blockDim.x + threadIdx.x;
    if (e < E) {
        int r = edge_at(e32, e64, e);
        int c = edge_at(e32, e64, E + e);
        g_csr[atomicAdd(&g_pos[c], 1)] = r;
    } else if (e < E + n) {
        int i = e - E;
        g_csr[atomicAdd(&g_pos[i], 1)] = i;     // self-loop
    }
}

// ---------------- fused layer: out = relu( agg(hin) @ W + b ) ----------------
// 64 nodes/block, 256 threads (8 warps x 8 nodes). Aggregate into smem, then
// 64x64x64 block GEMM with f32x2 packed FMA.
// hs padded to 68 floats/row: stride 272B is 16B-aligned for float4 access.
__device__ __forceinline__ void agg_to_smem(
    const float* __restrict__ hin, float hs[64][68],
    int row0, int n, int lane, int wid)
{
    const float2* __restrict__ h2 = (const float2*)hin;
    #pragma unroll
    for (int j = 0; j < 8; j++) {
        int row = wid * 8 + j;
        int i = row0 + row;
        float ax = 0.f, ay = 0.f;
        if (i < n) {
            const float di = __ldg(&g_dinv[i]);
            const int s = __ldg(&g_off[i]);
            const int e = s + __ldg(&g_deg[i]);
            for (int p = s; p < e; ++p) {
                int   src = __ldg(&g_csr[p]);
                float wt  = di * __ldg(&g_dinv[src]);
                float2 v  = __ldg(&h2[(size_t)src * 32 + lane]);
                ax = fmaf(v.x, wt, ax);
                ay = fmaf(v.y, wt, ay);
            }
        }
        *(float2*)&hs[row][2 * lane] = make_float2(ax, ay);
    }
}

// block GEMM: y[64][64] = hs @ Ws (+bias) (optional relu). Each thread: 4x4 tile.
__device__ __forceinline__ void tile_gemm(
    const float hs[64][68], const float Ws[64][64],
    const float* __restrict__ bias, int doRelu,
    int rt, int ct, float4 out[4])
{
    unsigned long long acc[4][2];
    #pragma unroll
    for (int r = 0; r < 4; r++) { acc[r][0] = 0ull; acc[r][1] = 0ull; }
    #pragma unroll
    for (int k = 0; k < 64; k += 2) {
        ulonglong2 w0 = *(const ulonglong2*)&Ws[k    ][ct * 4];
        ulonglong2 w1 = *(const ulonglong2*)&Ws[k + 1][ct * 4];
        #pragma unroll
        for (int r = 0; r < 4; r++) {
            float2 a2 = *(const float2*)&hs[rt * 4 + r][k];
            unsigned int a0u = __float_as_uint(a2.x);
            unsigned int a1u = __float_as_uint(a2.y);
            unsigned long long pa0, pa1;
            asm("mov.b64 %0, {%1,%1};" : "=l"(pa0) : "r"(a0u));
            asm("mov.b64 %0, {%1,%1};" : "=l"(pa1) : "r"(a1u));
            asm("fma.rn.f32x2 %0, %1, %2, %0;" : "+l"(acc[r][0]) : "l"(pa0), "l"(w0.x));
            asm("fma.rn.f32x2 %0, %1, %2, %0;" : "+l"(acc[r][1]) : "l"(pa0), "l"(w0.y));
            asm("fma.rn.f32x2 %0, %1, %2, %0;" : "+l"(acc[r][0]) : "l"(pa1), "l"(w1.x));
            asm("fma.rn.f32x2 %0, %1, %2, %0;" : "+l"(acc[r][1]) : "l"(pa1), "l"(w1.y));
        }
    }
    float bx = bias[ct * 4 + 0], by = bias[ct * 4 + 1];
    float bz = bias[ct * 4 + 2], bw = bias[ct * 4 + 3];
    #pragma unroll
    for (int r = 0; r < 4; r++) {
        float4 o;
        o.x = __uint_as_float((unsigned int)(acc[r][0]      )) + bx;
        o.y = __uint_as_float((unsigned int)(acc[r][0] >> 32)) + by;
        o.z = __uint_as_float((unsigned int)(acc[r][1]      )) + bz;
        o.w = __uint_as_float((unsigned int)(acc[r][1] >> 32)) + bw;
        if (doRelu) {
            o.x = fmaxf(o.x, 0.f); o.y = fmaxf(o.y, 0.f);
            o.z = fmaxf(o.z, 0.f); o.w = fmaxf(o.w, 0.f);
        }
        out[r] = o;
    }
}

__global__ void __launch_bounds__(256) k_layer(
    const float* __restrict__ hin, const float* __restrict__ W,
    const float* __restrict__ bias, float* __restrict__ hout, int n)
{
    __shared__ __align__(16) float Ws[64][64];
    __shared__ __align__(16) float hs[64][68];
    const int t = threadIdx.x;
    const int lane = t & 31, wid = t >> 5;
    const int row0 = blockIdx.x * 64;

    {   // load W
        const float4* W4 = (const float4*)W;
        float4* Ws4 = (float4*)Ws;
        #pragma unroll
        for (int i = t; i < 1024; i += 256) Ws4[i] = W4[i];
    }
    agg_to_smem(hin, hs, row0, n, lane, wid);
    __syncthreads();

    const int rt = t >> 4, ct = t & 15;
    float4 y[4];
    tile_gemm(hs, Ws, bias, 1, rt, ct, y);
    #pragma unroll
    for (int r = 0; r < 4; r++) {
        int row = row0 + rt * 4 + r;
        if (row < n) ((float4*)hout)[(size_t)row * 16 + ct] = y[r];
    }
}

// final layer: out1 = relu(agg(hin)@W2+b2); out2 = out1@Wl+bl
__global__ void __launch_bounds__(256) k_layer_final(
    const float* __restrict__ hin,
    const float* __restrict__ W2, const float* __restrict__ b2,
    const float* __restrict__ Wl, const float* __restrict__ bl,
    float* __restrict__ out1, float* __restrict__ out2, int n, int haveTwo)
{
    __shared__ __align__(16) float Ws[64][64];
    __shared__ __align__(16) float hs[64][68];
    const int t = threadIdx.x;
    const int lane = t & 31, wid = t >> 5;
    const int row0 = blockIdx.x * 64;

    {
        const float4* W4 = (const float4*)W2;
        float4* Ws4 = (float4*)Ws;
        #pragma unroll
        for (int i = t; i < 1024; i += 256) Ws4[i] = W4[i];
    }
    agg_to_smem(hin, hs, row0, n, lane, wid);
    __syncthreads();

    const int rt = t >> 4, ct = t & 15;
    float4 y[4];
    tile_gemm(hs, Ws, b2, 1, rt, ct, y);
    #pragma unroll
    for (int r = 0; r < 4; r++) {
        int row = row0 + rt * 4 + r;
        if (row < n) ((float4*)out1)[(size_t)row * 16 + ct] = y[r];
    }
    if (!haveTwo) return;

    __syncthreads();                       // everyone done reading hs
    #pragma unroll
    for (int r = 0; r < 4; r++)            // stash relu'd rows back into hs
        *(float4*)&hs[rt * 4 + r][ct * 4] = y[r];
    {   // swap W2 -> Wl in smem
        const float4* W4 = (const float4*)Wl;
        float4* Ws4 = (float4*)Ws;
        #pragma unroll
        for (int i = t; i < 1024; i += 256) Ws4[i] = W4[i];
    }
    __syncthreads();

    float4 z[4];
    tile_gemm(hs, Ws, bl, 0, rt, ct, z);
    #pragma unroll
    for (int r = 0; r < 4; r++) {
        int row = row0 + rt * 4 + r;
        if (row < n) ((float4*)out2)[(size_t)row * 16 + ct] = z[r];
    }
}

// ---------------- launch -----------------------------------------------------
extern "C" void kernel_launch(void* const* d_in, const int* in_sizes, int n_in,
                              void* d_out, int out_size)
{
    const float*     x    = (const float*)d_in[0];
    const int*       ei32 = (const int*)d_in[1];
    const long long* ei64 = (const long long*)d_in[1];
    const float* W0 = (const float*)d_in[3];
    const float* b0 = (const float*)d_in[4];
    const float* W1 = (const float*)d_in[5];
    const float* b1 = (const float*)d_in[6];
    const float* W2 = (const float*)d_in[7];
    const float* b2 = (const float*)d_in[8];
    const float* Wl = (const float*)d_in[9];
    const float* bl = (const float*)d_in[10];

    const int n = in_sizes[0] / HD;       // 100000
    const int E = in_sizes[1] / 2;        // 800000

    float* out1 = (float*)d_out;
    const int haveTwo = (out_size >= 2 * n * HD) ? 1 : 0;
    float* out2 = (float*)d_out + (size_t)n * HD;

    float* bufA; cudaGetSymbolAddress((void**)&bufA, g_bufA);
    float* bufB; cudaGetSymbolAddress((void**)&bufB, g_bufB);
    int*   degP; cudaGetSymbolAddress((void**)&degP, g_deg);

    const int T = 256;
    // CSR build
    k_detect<<<1, 32>>>(ei64, n);
    cudaMemsetAsync(degP, 0, (size_t)n * sizeof(int));
    k_count<<<(E + T - 1) / T, T>>>(ei32, ei64, E);
    const int nscan = (n + 1023) / 1024;
    k_scanA<<<nscan, 1024>>>(n);
    k_scanB<<<1, 128>>>(nscan);
    k_scanC<<<(n + T - 1) / T, T>>>(n);
    k_fill <<<(E + n + T - 1) / T, T>>>(ei32, ei64, E, n);

    const int B = (n + 63) / 64;
    // fused layers: relu(agg(h) @ W + b)
    k_layer<<<B, 256>>>(x,    W0, b0, bufA, n);
    k_layer<<<B, 256>>>(bufA, W1, b1, bufB, n);
    k_layer_final<<<B, 256>>>(bufB, W2, b2, Wl, bl, out1, out2, n, haveTwo);
}

// round 7
// speedup vs baseline: 1.1566x; 1.1566x over previous
#include <cuda_runtime.h>
#include <cstdint>

#define NN 100000
#define NE 800000
#define HD 64
#define CSR_CAP 2048   // smem-staged CSR segment per 64-node block (ints)

// ---------------- device scratch ---------------------------------------------
__device__ __align__(16) float g_bufA[(size_t)NN * HD];
__device__ __align__(16) float g_bufB[(size_t)NN * HD];
__device__ int   g_deg [NN];
__device__ float g_dinv[NN];
__device__ int   g_off [NN];
__device__ int   g_pos [NN];
__device__ int   g_csr [NE + NN];
__device__ int   g_bsum[128];
__device__ int   g_is64;

// ---------------- edge dtype detection (int32 vs int64) ----------------------
__global__ void k_detect(const long long* __restrict__ ei64, int n) {
    if (threadIdx.x == 0 && blockIdx.x == 0) {
        int is64 = 1;
        #pragma unroll
        for (int k = 0; k < 16; k++) {
            long long v = ei64[k];
            if (v < 0 || v >= (long long)n) { is64 = 0; break; }
        }
        g_is64 = is64;
    }
}

__device__ __forceinline__ int edge_at(const int* __restrict__ p32,
                                       const long long* __restrict__ p64,
                                       int idx) {
    return g_is64 ? (int)__ldg(&p64[idx]) : __ldg(&p32[idx]);
}

// ---------------- CSR construction -------------------------------------------
__global__ void k_count(const int* __restrict__ e32,
                        const long long* __restrict__ e64, int E) {
    int e = blockIdx.x * blockDim.x + threadIdx.x;
    if (e < E) atomicAdd(&g_deg[edge_at(e32, e64, E + e)], 1);
}

__global__ void __launch_bounds__(1024) k_scanA(int n) {
    __shared__ int wsum[32];
    int i    = blockIdx.x * 1024 + threadIdx.x;
    int lane = threadIdx.x & 31, wid = threadIdx.x >> 5;
    int v = 0;
    if (i < n) {
        v = g_deg[i] + 1;                 // +1 self-loop
        g_deg[i]  = v;
        g_dinv[i] = rsqrtf((float)v);
    }
    int s = v;
    #pragma unroll
    for (int d = 1; d < 32; d <<= 1) {
        int t = __shfl_up_sync(0xffffffffu, s, d);
        if (lane >= d) s += t;
    }
    if (lane == 31) wsum[wid] = s;
    __syncthreads();
    if (wid == 0) {
        int ws = wsum[lane];
        #pragma unroll
        for (int d = 1; d < 32; d <<= 1) {
            int t = __shfl_up_sync(0xffffffffu, ws, d);
            if (lane >= d) ws += t;
        }
        wsum[lane] = ws;
    }
    __syncthreads();
    if (i < n) g_off[i] = (wid ? wsum[wid - 1] : 0) + s - v;
    if (threadIdx.x == 0) g_bsum[blockIdx.x] = wsum[31];
}

__global__ void k_scanB(int nb) {
    __shared__ int wsum[4];
    int t = threadIdx.x, lane = t & 31, wid = t >> 5;
    int v = (t < nb) ? g_bsum[t] : 0;
    int s = v;
    #pragma unroll
    for (int d = 1; d < 32; d <<= 1) {
        int u = __shfl_up_sync(0xffffffffu, s, d);
        if (lane >= d) s += u;
    }
    if (lane == 31) wsum[wid] = s;
    __syncthreads();
    if (t == 0) { int r = 0; for (int w = 0; w < 4; w++) { int x = wsum[w]; wsum[w] = r; r += x; } }
    __syncthreads();
    if (t < nb) g_bsum[t] = wsum[wid] + s - v;
}

__global__ void k_scanC(int n) {
    int i = blockIdx.x * blockDim.x + threadIdx.x;
    if (i < n) {
        int o = g_off[i] + g_bsum[i >> 10];
        g_off[i] = o;
        g_pos[i] = o;
    }
}

__global__ void k_fill(const int* __restrict__ e32,
                       const long long* __restrict__ e64, int E, int n) {
    int e = blockIdx.x * blockDim.x + threadIdx.x;
    if (e < E) {
        int r = edge_at(e32, e64, e);
        int c = edge_at(e32, e64, E + e);
        g_csr[atomicAdd(&g_pos[c], 1)] = r;
    } else if (e < E + n) {
        int i = e - E;
        g_csr[atomicAdd(&g_pos[i], 1)] = i;
    }
}

// ---------------- prescale: xs[i] = x[i] * dinv[node] -------------------------
__global__ void k_pre(const float4* __restrict__ x4, float4* __restrict__ xs4,
                      int n) {
    int i = blockIdx.x * blockDim.x + threadIdx.x;   // over n*16 float4s
    if (i < n * 16) {
        float d = g_dinv[i >> 4];
        float4 v = __ldg(&x4[i]);
        v.x *= d; v.y *= d; v.z *= d; v.w *= d;
        xs4[i] = v;
    }
}

// ---------------- fused layer -------------------------------------------------
// Input hin is PRE-SCALED (rows already multiplied by their dinv).
// out_row = relu( dinv[row] * (sum_{src} hin[src]) @ W + b )
// Stored (mid layers): out_row * dinv[row]   (pre-scale for next layer)
//
// 64 nodes/block, 256 threads. Gather: half-warp (16 lanes, float4) per node,
// CSR segment staged in smem, unroll-by-4 for MLP. Then 64x64x64 smem GEMM.

__device__ __forceinline__ void gather_phase(
    const float* __restrict__ hin, float hs[64][68],
    int* s_csr, int* s_off, int* s_deg,
    int row0, int n, int t)
{
    // stage per-node offsets/degrees
    if (t < 64) {
        int i = row0 + t;
        s_off[t] = (i < n) ? g_off[i] : 0;
        s_deg[t] = (i < n) ? g_deg[i] : 0;
    }
    __syncthreads();
    int lastRow = (row0 + 63 < n) ? 63 : (n - 1 - row0);
    int base = s_off[0];
    int tot  = (lastRow >= 0) ? (s_off[lastRow] - base + s_deg[lastRow]) : 0;
    bool useS = (tot <= CSR_CAP);
    if (useS) {
        for (int i = t; i < tot; i += 256) s_csr[i] = __ldg(&g_csr[base + i]);
    }
    __syncthreads();

    const float4* __restrict__ h4 = (const float4*)hin;
    const int hw = t >> 4;          // half-warp id 0..15
    const int lane16 = t & 15;

    #pragma unroll
    for (int j = 0; j < 4; j++) {
        int row = hw * 4 + j;
        float4 a = make_float4(0.f, 0.f, 0.f, 0.f);
        if (row0 + row < n) {
            int d = s_deg[row];
            int p = 0;
            if (useS) {
                int s = s_off[row] - base;
                for (; p + 4 <= d; p += 4) {
                    int s0 = s_csr[s + p + 0];
                    int s1 = s_csr[s + p + 1];
                    int s2 = s_csr[s + p + 2];
                    int s3 = s_csr[s + p + 3];
                    float4 v0 = __ldg(&h4[(size_t)s0 * 16 + lane16]);
                    float4 v1 = __ldg(&h4[(size_t)s1 * 16 + lane16]);
                    float4 v2 = __ldg(&h4[(size_t)s2 * 16 + lane16]);
                    float4 v3 = __ldg(&h4[(size_t)s3 * 16 + lane16]);
                    a.x += (v0.x + v1.x) + (v2.x + v3.x);
                    a.y += (v0.y + v1.y) + (v2.y + v3.y);
                    a.z += (v0.z + v1.z) + (v2.z + v3.z);
                    a.w += (v0.w + v1.w) + (v2.w + v3.w);
                }
                for (; p < d; p++) {
                    float4 v = __ldg(&h4[(size_t)s_csr[s + p] * 16 + lane16]);
                    a.x += v.x; a.y += v.y; a.z += v.z; a.w += v.w;
                }
            } else {
                int s = s_off[row];
                for (; p + 4 <= d; p += 4) {
                    int s0 = __ldg(&g_csr[s + p + 0]);
                    int s1 = __ldg(&g_csr[s + p + 1]);
                    int s2 = __ldg(&g_csr[s + p + 2]);
                    int s3 = __ldg(&g_csr[s + p + 3]);
                    float4 v0 = __ldg(&h4[(size_t)s0 * 16 + lane16]);
                    float4 v1 = __ldg(&h4[(size_t)s1 * 16 + lane16]);
                    float4 v2 = __ldg(&h4[(size_t)s2 * 16 + lane16]);
                    float4 v3 = __ldg(&h4[(size_t)s3 * 16 + lane16]);
                    a.x += (v0.x + v1.x) + (v2.x + v3.x);
                    a.y += (v0.y + v1.y) + (v2.y + v3.y);
                    a.z += (v0.z + v1.z) + (v2.z + v3.z);
                    a.w += (v0.w + v1.w) + (v2.w + v3.w);
                }
                for (; p < d; p++) {
                    float4 v = __ldg(&h4[(size_t)__ldg(&g_csr[s + p]) * 16 + lane16]);
                    a.x += v.x; a.y += v.y; a.z += v.z; a.w += v.w;
                }
            }
        }
        *(float4*)&hs[row][lane16 * 4] = a;
    }
}

// block GEMM: raw = hs @ Ws, per-thread 4x4 tile. No epilogue.
__device__ __forceinline__ void tile_gemm_raw(
    const float hs[64][68], const float Ws[64][64],
    int rt, int ct, float4 out[4])
{
    unsigned long long acc[4][2];
    #pragma unroll
    for (int r = 0; r < 4; r++) { acc[r][0] = 0ull; acc[r][1] = 0ull; }
    #pragma unroll
    for (int k = 0; k < 64; k += 2) {
        ulonglong2 w0 = *(const ulonglong2*)&Ws[k    ][ct * 4];
        ulonglong2 w1 = *(const ulonglong2*)&Ws[k + 1][ct * 4];
        #pragma unroll
        for (int r = 0; r < 4; r++) {
            float2 a2 = *(const float2*)&hs[rt * 4 + r][k];
            unsigned int a0u = __float_as_uint(a2.x);
            unsigned int a1u = __float_as_uint(a2.y);
            unsigned long long pa0, pa1;
            asm("mov.b64 %0, {%1,%1};" : "=l"(pa0) : "r"(a0u));
            asm("mov.b64 %0, {%1,%1};" : "=l"(pa1) : "r"(a1u));
            asm("fma.rn.f32x2 %0, %1, %2, %0;" : "+l"(acc[r][0]) : "l"(pa0), "l"(w0.x));
            asm("fma.rn.f32x2 %0, %1, %2, %0;" : "+l"(acc[r][1]) : "l"(pa0), "l"(w0.y));
            asm("fma.rn.f32x2 %0, %1, %2, %0;" : "+l"(acc[r][0]) : "l"(pa1), "l"(w1.x));
            asm("fma.rn.f32x2 %0, %1, %2, %0;" : "+l"(acc[r][1]) : "l"(pa1), "l"(w1.y));
        }
    }
    #pragma unroll
    for (int r = 0; r < 4; r++) {
        out[r].x = __uint_as_float((unsigned int)(acc[r][0]      ));
        out[r].y = __uint_as_float((unsigned int)(acc[r][0] >> 32));
        out[r].z = __uint_as_float((unsigned int)(acc[r][1]      ));
        out[r].w = __uint_as_float((unsigned int)(acc[r][1] >> 32));
    }
}

// mid layer: hout = relu(dinv[row]*(agg@W)+b) * dinv[row]
__global__ void __launch_bounds__(256) k_layer(
    const float* __restrict__ hin, const float* __restrict__ W,
    const float* __restrict__ bias, float* __restrict__ hout, int n)
{
    __shared__ __align__(16) float Ws[64][64];
    __shared__ __align__(16) float hs[64][68];
    __shared__ int s_csr[CSR_CAP];
    __shared__ int s_off[64], s_deg[64];
    const int t = threadIdx.x;
    const int row0 = blockIdx.x * 64;

    {
        const float4* W4 = (const float4*)W;
        float4* Ws4 = (float4*)Ws;
        #pragma unroll
        for (int i = t; i < 1024; i += 256) Ws4[i] = W4[i];
    }
    gather_phase(hin, hs, s_csr, s_off, s_deg, row0, n, t);
    __syncthreads();

    const int rt = t >> 4, ct = t & 15;
    float4 y[4];
    tile_gemm_raw(hs, Ws, rt, ct, y);
    float bx = bias[ct * 4 + 0], by = bias[ct * 4 + 1];
    float bz = bias[ct * 4 + 2], bw = bias[ct * 4 + 3];
    #pragma unroll
    for (int r = 0; r < 4; r++) {
        int row = row0 + rt * 4 + r;
        if (row < n) {
            float c = __ldg(&g_dinv[row]);
            float4 o;
            o.x = fmaxf(fmaf(y[r].x, c, bx), 0.f) * c;
            o.y = fmaxf(fmaf(y[r].y, c, by), 0.f) * c;
            o.z = fmaxf(fmaf(y[r].z, c, bz), 0.f) * c;
            o.w = fmaxf(fmaf(y[r].w, c, bw), 0.f) * c;
            ((float4*)hout)[(size_t)row * 16 + ct] = o;
        }
    }
}

// final: out1 = relu(dinv*(agg@W2)+b2) ; out2 = out1@Wl+bl
__global__ void __launch_bounds__(256) k_layer_final(
    const float* __restrict__ hin,
    const float* __restrict__ W2, const float* __restrict__ b2,
    const float* __restrict__ Wl, const float* __restrict__ bl,
    float* __restrict__ out1, float* __restrict__ out2, int n, int haveTwo)
{
    __shared__ __align__(16) float Ws[64][64];
    __shared__ __align__(16) float hs[64][68];
    __shared__ int s_csr[CSR_CAP];
    __shared__ int s_off[64], s_deg[64];
    const int t = threadIdx.x;
    const int row0 = blockIdx.x * 64;

    {
        const float4* W4 = (const float4*)W2;
        float4* Ws4 = (float4*)Ws;
        #pragma unroll
        for (int i = t; i < 1024; i += 256) Ws4[i] = W4[i];
    }
    gather_phase(hin, hs, s_csr, s_off, s_deg, row0, n, t);
    __syncthreads();

    const int rt = t >> 4, ct = t & 15;
    float4 y[4];
    tile_gemm_raw(hs, Ws, rt, ct, y);
    {
        float bx = b2[ct * 4 + 0], by = b2[ct * 4 + 1];
        float bz = b2[ct * 4 + 2], bw = b2[ct * 4 + 3];
        #pragma unroll
        for (int r = 0; r < 4; r++) {
            int row = row0 + rt * 4 + r;
            float c = (row < n) ? __ldg(&g_dinv[row]) : 0.f;
            y[r].x = fmaxf(fmaf(y[r].x, c, bx), 0.f);
            y[r].y = fmaxf(fmaf(y[r].y, c, by), 0.f);
            y[r].z = fmaxf(fmaf(y[r].z, c, bz), 0.f);
            y[r].w = fmaxf(fmaf(y[r].w, c, bw), 0.f);
            if (row < n) ((float4*)out1)[(size_t)row * 16 + ct] = y[r];
        }
    }
    if (!haveTwo) return;

    __syncthreads();
    #pragma unroll
    for (int r = 0; r < 4; r++)
        *(float4*)&hs[rt * 4 + r][ct * 4] = y[r];
    {
        const float4* W4 = (const float4*)Wl;
        float4* Ws4 = (float4*)Ws;
        #pragma unroll
        for (int i = t; i < 1024; i += 256) Ws4[i] = W4[i];
    }
    __syncthreads();

    float4 z[4];
    tile_gemm_raw(hs, Ws, rt, ct, z);
    float bx = bl[ct * 4 + 0], by = bl[ct * 4 + 1];
    float bz = bl[ct * 4 + 2], bw = bl[ct * 4 + 3];
    #pragma unroll
    for (int r = 0; r < 4; r++) {
        int row = row0 + rt * 4 + r;
        if (row < n) {
            float4 o;
            o.x = z[r].x + bx; o.y = z[r].y + by;
            o.z = z[r].z + bz; o.w = z[r].w + bw;
            ((float4*)out2)[(size_t)row * 16 + ct] = o;
        }
    }
}

// ---------------- launch -----------------------------------------------------
extern "C" void kernel_launch(void* const* d_in, const int* in_sizes, int n_in,
                              void* d_out, int out_size)
{
    const float*     x    = (const float*)d_in[0];
    const int*       ei32 = (const int*)d_in[1];
    const long long* ei64 = (const long long*)d_in[1];
    const float* W0 = (const float*)d_in[3];
    const float* b0 = (const float*)d_in[4];
    const float* W1 = (const float*)d_in[5];
    const float* b1 = (const float*)d_in[6];
    const float* W2 = (const float*)d_in[7];
    const float* b2 = (const float*)d_in[8];
    const float* Wl = (const float*)d_in[9];
    const float* bl = (const float*)d_in[10];

    const int n = in_sizes[0] / HD;       // 100000
    const int E = in_sizes[1] / 2;        // 800000

    float* out1 = (float*)d_out;
    const int haveTwo = (out_size >= 2 * n * HD) ? 1 : 0;
    float* out2 = (float*)d_out + (size_t)n * HD;

    float* bufA; cudaGetSymbolAddress((void**)&bufA, g_bufA);
    float* bufB; cudaGetSymbolAddress((void**)&bufB, g_bufB);
    int*   degP; cudaGetSymbolAddress((void**)&degP, g_deg);

    const int T = 256;
    // CSR build
    k_detect<<<1, 32>>>(ei64, n);
    cudaMemsetAsync(degP, 0, (size_t)n * sizeof(int));
    k_count<<<(E + T - 1) / T, T>>>(ei32, ei64, E);
    const int nscan = (n + 1023) / 1024;
    k_scanA<<<nscan, 1024>>>(n);
    k_scanB<<<1, 128>>>(nscan);
    k_scanC<<<(n + T - 1) / T, T>>>(n);
    k_fill <<<(E + n + T - 1) / T, T>>>(ei32, ei64, E, n);

    // prescale x by dinv -> bufA
    k_pre<<<(n * 16 + T - 1) / T, T>>>((const float4*)x, (float4*)bufA, n);

    const int B = (n + 63) / 64;
    // bufA(xs) -> bufB -> bufA -> out
    k_layer<<<B, 256>>>(bufA, W0, b0, bufB, n);
    k_layer<<<B, 256>>>(bufB, W1, b1, bufA, n);
    k_layer_final<<<B, 256>>>(bufA, W2, b2, Wl, bl, out1, out2, n, haveTwo);
}